// round 15
// baseline (speedup 1.0000x reference)
#include <cuda_runtime.h>
#include <cuda_fp16.h>

#define N_NODES 100000
#define N_EDGES 1600000
#define DIM 64
#define SCAN_T 1024
#define NB_PROP (148 * 4)   // 4 blocks/SM — occupancy experiment (R13 was 12500)

// ---------------- device scratch (static, no allocation) ----------------
__device__ int      g_is64;
__device__ int      g_deg[N_NODES];
__device__ int      g_cursor[N_NODES];
__device__ float    g_dinv[N_NODES];
__device__ int      g_indptr[N_NODES + 1];
__device__ int      g_bsum[128];
__device__ unsigned long long g_edges[N_EDGES];   // hi32: dinv[src] bits, lo32: src
// 5 feature planes in fp16 (raw u32 = 2 halves along feature dim): 0:X 1:P1 2:P3 3:A 4:B
__device__ unsigned g_h[5][N_NODES * 32];
// folded weights, fp16, B-fragment-paired: [s][n][kk][th4]
__device__ uint2    g_Wp[4 * 64 * 4 * 4];

__device__ __forceinline__ __half2 h2_of(unsigned u) {
    return *reinterpret_cast<__half2*>(&u);
}
__device__ __forceinline__ unsigned u_of(__half2 h) {
    return *reinterpret_cast<unsigned*>(&h);
}

// ---------------- fused init: zero counters + x->fp16 + dtype probe ----------
__global__ void k_init(const unsigned* __restrict__ w, const float* __restrict__ x) {
    int tid  = blockIdx.x * blockDim.x + threadIdx.x;
    int nthr = gridDim.x * blockDim.x;

    for (int i = tid; i < N_NODES; i += nthr) { g_deg[i] = 0; g_cursor[i] = 0; }

    const float2* x2 = (const float2*)x;
    for (int i = tid; i < N_NODES * 32; i += nthr) {
        float2 v = x2[i];
        g_h[0][i] = u_of(__floats2half2_rn(v.x, v.y));
    }

    if (blockIdx.x == 0) {
        __shared__ int s_any;
        if (threadIdx.x == 0) s_any = 0;
        __syncthreads();
        if (threadIdx.x < 128) {
            unsigned v = w[2 * threadIdx.x + 1];          // odd words, first 128 pairs
            unsigned any = __ballot_sync(0xFFFFFFFFu, v != 0);
            if ((threadIdx.x & 31) == 0 && any) atomicExch(&s_any, 1);
        }
        __syncthreads();
        if (threadIdx.x == 0) g_is64 = s_any ? 0 : 1;
    }
}

__device__ __forceinline__ int edge_at(const void* ei, int idx, int is64) {
    if (is64) return (int)((const long long*)ei)[idx];
    return ((const int*)ei)[idx];
}

// ---------------- CSR build ----------------
__global__ void k_hist(const void* __restrict__ ei) {
    int e = blockIdx.x * blockDim.x + threadIdx.x;
    if (e < N_EDGES) {
        int is64 = g_is64;
        int dst = edge_at(ei, N_EDGES + e, is64);
        if ((unsigned)dst < N_NODES) atomicAdd(&g_deg[dst], 1);
    }
}

__global__ void k_scan1() {
    __shared__ int s[SCAN_T];
    int t = threadIdx.x;
    int idx = blockIdx.x * SCAN_T + t;
    int v = (idx < N_NODES) ? g_deg[idx] : 0;
    s[t] = v;
    __syncthreads();
    for (int off = 1; off < SCAN_T; off <<= 1) {
        int xv = (t >= off) ? s[t - off] : 0;
        __syncthreads();
        s[t] += xv;
        __syncthreads();
    }
    if (idx < N_NODES) {
        g_indptr[idx] = s[t] - v;                          // local exclusive
        g_dinv[idx]   = rsqrtf((float)(v + 1));            // +1 self-loop
    }
    if (t == SCAN_T - 1) g_bsum[blockIdx.x] = s[t];
}

// parallel cross-block offset: threads 0..127 reduce g_bsum[0..bid-1]
__global__ void k_scanfix() {
    __shared__ int s_part[4];
    __shared__ int s_off;
    int t   = threadIdx.x;
    int bid = blockIdx.x;
    if (t < 128) {
        int v = (t < bid) ? g_bsum[t] : 0;
#pragma unroll
        for (int o = 16; o > 0; o >>= 1) v += __shfl_down_sync(0xFFFFFFFFu, v, o);
        if ((t & 31) == 0) s_part[t >> 5] = v;
    }
    __syncthreads();
    if (t == 0) s_off = s_part[0] + s_part[1] + s_part[2] + s_part[3];
    __syncthreads();
    int idx = bid * SCAN_T + t;
    if (idx < N_NODES) g_indptr[idx] += s_off;
    if (idx == 0) g_indptr[N_NODES] = N_EDGES;
}

__global__ void k_scatter(const void* __restrict__ ei) {
    int e = blockIdx.x * blockDim.x + threadIdx.x;
    if (e < N_EDGES) {
        int is64 = g_is64;
        int src = edge_at(ei, e, is64);
        int dst = edge_at(ei, N_EDGES + e, is64);
        if ((unsigned)src < N_NODES && (unsigned)dst < N_NODES) {
            int pos = g_indptr[dst] + atomicAdd(&g_cursor[dst], 1);
            unsigned wbits = __float_as_uint(g_dinv[src]);
            g_edges[pos] = ((unsigned long long)wbits << 32) | (unsigned)src;
        }
    }
}

// ---------------- SpMM (pull, warp-per-node, half2 per lane, MLP=8) ---------
// R10 inner body EXACT (protected); only change: persistent outer grid-stride
// loop at 4 blocks/SM to test the cross-CTA L1tex-queue-contention theory.
// out[i] = dinv[i] * ( sum_e dinv[src_e] * h[src_e] + dinv[i] * h[i] )
__global__ void __launch_bounds__(256)
k_prop(int sel_in, int sel_out) {
    const unsigned* hin  = g_h[sel_in];
    unsigned*       hout = g_h[sel_out];

    int lane = threadIdx.x & 31;
    int warpsTotal = (gridDim.x * blockDim.x) >> 5;
    for (int gw = (blockIdx.x * blockDim.x + threadIdx.x) >> 5; gw < N_NODES;
         gw += warpsTotal) {

        int beg = g_indptr[gw];
        int end = g_indptr[gw + 1];

        float ax = 0.f, ay = 0.f;
        int e = beg;
        for (; e + 8 <= end; e += 8) {
            unsigned long long p0 = __ldg(&g_edges[e]);
            unsigned long long p1 = __ldg(&g_edges[e + 1]);
            unsigned long long p2 = __ldg(&g_edges[e + 2]);
            unsigned long long p3 = __ldg(&g_edges[e + 3]);
            unsigned long long p4 = __ldg(&g_edges[e + 4]);
            unsigned long long p5 = __ldg(&g_edges[e + 5]);
            unsigned long long p6 = __ldg(&g_edges[e + 6]);
            unsigned long long p7 = __ldg(&g_edges[e + 7]);
            unsigned u0 = __ldg(&hin[((int)(unsigned)p0) * 32 + lane]);
            unsigned u1 = __ldg(&hin[((int)(unsigned)p1) * 32 + lane]);
            unsigned u2 = __ldg(&hin[((int)(unsigned)p2) * 32 + lane]);
            unsigned u3 = __ldg(&hin[((int)(unsigned)p3) * 32 + lane]);
            unsigned u4 = __ldg(&hin[((int)(unsigned)p4) * 32 + lane]);
            unsigned u5 = __ldg(&hin[((int)(unsigned)p5) * 32 + lane]);
            unsigned u6 = __ldg(&hin[((int)(unsigned)p6) * 32 + lane]);
            unsigned u7 = __ldg(&hin[((int)(unsigned)p7) * 32 + lane]);
            float w0 = __uint_as_float((unsigned)(p0 >> 32));
            float w1 = __uint_as_float((unsigned)(p1 >> 32));
            float w2 = __uint_as_float((unsigned)(p2 >> 32));
            float w3 = __uint_as_float((unsigned)(p3 >> 32));
            float w4 = __uint_as_float((unsigned)(p4 >> 32));
            float w5 = __uint_as_float((unsigned)(p5 >> 32));
            float w6 = __uint_as_float((unsigned)(p6 >> 32));
            float w7 = __uint_as_float((unsigned)(p7 >> 32));
            float2 f0 = __half22float2(h2_of(u0));
            float2 f1 = __half22float2(h2_of(u1));
            float2 f2 = __half22float2(h2_of(u2));
            float2 f3 = __half22float2(h2_of(u3));
            float2 f4 = __half22float2(h2_of(u4));
            float2 f5 = __half22float2(h2_of(u5));
            float2 f6 = __half22float2(h2_of(u6));
            float2 f7 = __half22float2(h2_of(u7));
            ax = fmaf(w0, f0.x, ax); ay = fmaf(w0, f0.y, ay);
            ax = fmaf(w1, f1.x, ax); ay = fmaf(w1, f1.y, ay);
            ax = fmaf(w2, f2.x, ax); ay = fmaf(w2, f2.y, ay);
            ax = fmaf(w3, f3.x, ax); ay = fmaf(w3, f3.y, ay);
            ax = fmaf(w4, f4.x, ax); ay = fmaf(w4, f4.y, ay);
            ax = fmaf(w5, f5.x, ax); ay = fmaf(w5, f5.y, ay);
            ax = fmaf(w6, f6.x, ax); ay = fmaf(w6, f6.y, ay);
            ax = fmaf(w7, f7.x, ax); ay = fmaf(w7, f7.y, ay);
        }
        for (; e < end; e++) {
            unsigned long long p = __ldg(&g_edges[e]);
            float2 f = __half22float2(h2_of(__ldg(&hin[((int)(unsigned)p) * 32 + lane])));
            float w = __uint_as_float((unsigned)(p >> 32));
            ax = fmaf(w, f.x, ax); ay = fmaf(w, f.y, ay);
        }

        float di = g_dinv[gw];
        float2 self = __half22float2(h2_of(__ldg(&hin[gw * 32 + lane])));
        ax = di * fmaf(di, self.x, ax);
        ay = di * fmaf(di, self.y, ay);
        hout[gw * 32 + lane] = u_of(__floats2half2_rn(ax, ay));
    }
}

// ---------------- weight folding: K=384 -> K=256, fp16, B-pair layout --------
// out = x*A + P1*B + P3*C + P7*D
__device__ __forceinline__ float fold_w(const float* W, int s, int k, int j) {
    float w0 = W[(0   + k) * 64 + j];
    float w1 = W[(64  + k) * 64 + j];
    float w2 = W[(128 + k) * 64 + j];
    float w3 = W[(192 + k) * 64 + j];
    float w4 = W[(256 + k) * 64 + j];
    float w5 = W[(320 + k) * 64 + j];
    if (s == 0) return w3;
    if (s == 1) return w0 - w3 + w4;
    if (s == 2) return w1 - w4 + w5;
    return w2 - w5;
}

__global__ void k_comb(const float* __restrict__ W) {
    int idx = blockIdx.x * blockDim.x + threadIdx.x;   // 4*64*4*4 = 4096
    if (idx >= 4 * 64 * 4 * 4) return;
    int s   = idx >> 10;
    int n   = (idx >> 4) & 63;
    int kk  = (idx >> 2) & 3;
    int th4 = idx & 3;
    int kc0 = kk * 8 + th4;       // b0 column-chunk
    int kc1 = kc0 + 4;            // b1 column-chunk
    uint2 p;
    p.x = u_of(__floats2half2_rn(fold_w(W, s, 2 * kc0, n), fold_w(W, s, 2 * kc0 + 1, n)));
    p.y = u_of(__floats2half2_rn(fold_w(W, s, 2 * kc1, n), fold_w(W, s, 2 * kc1 + 1, n)));
    g_Wp[idx] = p;
}

// ---------------- HMMA output GEMM: M=100000, N=64, K=4x64 + bias + relu -----
// block = 256 thr (8 warps), each warp: 16 rows x 64 cols, mma.m16n8k16 f16->f32
__global__ void __launch_bounds__(256)
k_gemm(const float* __restrict__ bias, float* __restrict__ out) {
    int w    = threadIdx.x >> 5;
    int t    = threadIdx.x & 31;
    int m0   = blockIdx.x * 128 + w * 16;
    int quad = t >> 2;          // 0..7
    int th4  = t & 3;           // 0..3

    int r0 = m0 + quad;
    int r1 = r0 + 8;
    int r0c = (r0 < N_NODES) ? r0 : 0;   // clamped for loads
    int r1c = (r1 < N_NODES) ? r1 : 0;

    float acc[8][4];
#pragma unroll
    for (int nt = 0; nt < 8; nt++)
#pragma unroll
        for (int i = 0; i < 4; i++) acc[nt][i] = 0.f;

    const int plane_sel[4] = {0, 1, 2, 4};
#pragma unroll
    for (int s = 0; s < 4; s++) {
        const unsigned* plane = g_h[plane_sel[s]];
        const uint2* Wb = &g_Wp[s * 64 * 16];
#pragma unroll
        for (int kk = 0; kk < 4; kk++) {
            int c0 = kk * 8 + th4;
            unsigned a0 = __ldg(&plane[r0c * 32 + c0]);
            unsigned a1 = __ldg(&plane[r1c * 32 + c0]);
            unsigned a2 = __ldg(&plane[r0c * 32 + c0 + 4]);
            unsigned a3 = __ldg(&plane[r1c * 32 + c0 + 4]);
#pragma unroll
            for (int nt = 0; nt < 8; nt++) {
                int n = nt * 8 + quad;
                uint2 bb = __ldg(&Wb[n * 16 + kk * 4 + th4]);
                asm volatile(
                    "mma.sync.aligned.m16n8k16.row.col.f32.f16.f16.f32 "
                    "{%0,%1,%2,%3}, {%4,%5,%6,%7}, {%8,%9}, {%0,%1,%2,%3};"
                    : "+f"(acc[nt][0]), "+f"(acc[nt][1]),
                      "+f"(acc[nt][2]), "+f"(acc[nt][3])
                    : "r"(a0), "r"(a1), "r"(a2), "r"(a3), "r"(bb.x), "r"(bb.y));
            }
        }
    }

#pragma unroll
    for (int nt = 0; nt < 8; nt++) {
        int col = nt * 8 + th4 * 2;
        float2 bj = __ldg((const float2*)&bias[col]);
        if (r0 < N_NODES) {
            float v0 = acc[nt][0] + bj.x;
            float v1 = acc[nt][1] + bj.y;
            float2 o; o.x = v0 > 0.f ? v0 : 0.f; o.y = v1 > 0.f ? v1 : 0.f;
            *(float2*)&out[r0 * 64 + col] = o;
        }
        if (r1 < N_NODES) {
            float v2 = acc[nt][2] + bj.x;
            float v3 = acc[nt][3] + bj.y;
            float2 o; o.x = v2 > 0.f ? v2 : 0.f; o.y = v3 > 0.f ? v3 : 0.f;
            *(float2*)&out[r1 * 64 + col] = o;
        }
    }
}

// ---------------- launch ----------------
extern "C" void kernel_launch(void* const* d_in, const int* in_sizes, int n_in,
                              void* d_out, int out_size) {
    const float* x  = (const float*)d_in[0];
    const void*  ei = d_in[1];
    const float* W  = (const float*)d_in[2];
    const float* b  = (const float*)d_in[3];
    float* out = (float*)d_out;

    int nb_edges = (N_EDGES + 255) / 256;
    int nb_scan  = (N_NODES + SCAN_T - 1) / SCAN_T;

    // CSR prologue
    k_init<<<512, 256>>>((const unsigned*)ei, x);      // 0
    k_hist<<<nb_edges, 256>>>(ei);                     // 1
    k_scan1<<<nb_scan, SCAN_T>>>();                    // 2
    k_scanfix<<<nb_scan, SCAN_T>>>();                  // 3
    k_scatter<<<nb_edges, 256>>>(ei);                  // 4

    // 7 propagations: save P^1 (plane1), P^3 (plane2), end at P^7 (plane4)
    k_prop<<<NB_PROP, 256>>>(0, 1);   // X  -> P1
    k_prop<<<NB_PROP, 256>>>(1, 3);   // P1 -> A   (P^2)
    k_prop<<<NB_PROP, 256>>>(3, 2);   // A  -> P3  (P^3)
    k_prop<<<NB_PROP, 256>>>(2, 3);   // P3 -> A   (P^4)
    k_prop<<<NB_PROP, 256>>>(3, 4);   // A  -> B   (P^5)
    k_prop<<<NB_PROP, 256>>>(4, 3);   // B  -> A   (P^6)
    k_prop<<<NB_PROP, 256>>>(3, 4);   // A  -> B   (P^7)

    k_comb<<<16, 256>>>(W);
    k_gemm<<<(N_NODES + 127) / 128, 256>>>(b, out);
}

// round 16
// speedup vs baseline: 1.3185x; 1.3185x over previous
#include <cuda_runtime.h>
#include <cuda_fp16.h>

#define N_NODES 100000
#define N_EDGES 1600000
#define DIM 64
#define SCAN_T 1024

// ---------------- device scratch (static, no allocation) ----------------
// g_deg / g_cursor are zero on first use (static zero-init) and re-zeroed at
// the END of every kernel_launch (inside k_gemm), keeping replays deterministic.
__device__ int      g_deg[N_NODES];
__device__ int      g_cursor[N_NODES];
__device__ float    g_dinv[N_NODES];
__device__ int      g_indptr[N_NODES + 1];
__device__ int      g_bsum[128];
__device__ unsigned long long g_edges[N_EDGES];   // hi32: dinv[src] bits, lo32: src
// 5 feature planes in fp16 (raw u32 = 2 halves along feature dim): 0:X 1:P1 2:P3 3:A 4:B
__device__ unsigned g_h[5][N_NODES * 32];
// folded weights, fp16, B-fragment-paired: [s][n][kk][th4]
__device__ uint2    g_Wp[4 * 64 * 4 * 4];

__device__ __forceinline__ __half2 h2_of(unsigned u) {
    return *reinterpret_cast<__half2*>(&u);
}
__device__ __forceinline__ unsigned u_of(__half2 h) {
    return *reinterpret_cast<unsigned*>(&h);
}

// Block-local dtype probe: for int64 node indices < 100000 (LE), every odd
// 32-bit word of edge_index is 0. 32 odd words all-zero for int32 data has
// probability ~(1e-5)^32 — effectively impossible.
__device__ __forceinline__ int probe_is64(const unsigned* w, int lane_tid) {
    __shared__ int s_is64;
    if (lane_tid < 32) {
        unsigned v = w[2 * lane_tid + 1];
        unsigned any = __ballot_sync(0xFFFFFFFFu, v != 0);
        if (lane_tid == 0) s_is64 = (any == 0) ? 1 : 0;
    }
    __syncthreads();
    return s_is64;
}

__device__ __forceinline__ int edge_at(const void* ei, int idx, int is64) {
    if (is64) return (int)((const long long*)ei)[idx];
    return ((const int*)ei)[idx];
}

// ---------------- fused init: x->fp16 + degree histogram ---------------------
// (g_deg arrives zeroed: first run by static init, later runs by k_gemm reset)
__global__ void k_init_hist(const void* __restrict__ ei, const float* __restrict__ x) {
    int is64 = probe_is64((const unsigned*)ei, threadIdx.x);
    int tid  = blockIdx.x * blockDim.x + threadIdx.x;
    int nthr = gridDim.x * blockDim.x;

    const float2* x2 = (const float2*)x;
    for (int i = tid; i < N_NODES * 32; i += nthr) {
        float2 v = x2[i];
        g_h[0][i] = u_of(__floats2half2_rn(v.x, v.y));
    }
    for (int e = tid; e < N_EDGES; e += nthr) {
        int dst = edge_at(ei, N_EDGES + e, is64);
        if ((unsigned)dst < N_NODES) atomicAdd(&g_deg[dst], 1);
    }
}

// ---------------- CSR build ----------------
__global__ void k_scan1() {
    __shared__ int s[SCAN_T];
    int t = threadIdx.x;
    int idx = blockIdx.x * SCAN_T + t;
    int v = (idx < N_NODES) ? g_deg[idx] : 0;
    s[t] = v;
    __syncthreads();
    for (int off = 1; off < SCAN_T; off <<= 1) {
        int xv = (t >= off) ? s[t - off] : 0;
        __syncthreads();
        s[t] += xv;
        __syncthreads();
    }
    if (idx < N_NODES) {
        g_indptr[idx] = s[t] - v;                          // local exclusive
        g_dinv[idx]   = rsqrtf((float)(v + 1));            // +1 self-loop
    }
    if (t == SCAN_T - 1) g_bsum[blockIdx.x] = s[t];
}

// parallel cross-block offset: threads 0..127 reduce g_bsum[0..bid-1]
__global__ void k_scanfix() {
    __shared__ int s_part[4];
    __shared__ int s_off;
    int t   = threadIdx.x;
    int bid = blockIdx.x;
    if (t < 128) {
        int v = (t < bid) ? g_bsum[t] : 0;
#pragma unroll
        for (int o = 16; o > 0; o >>= 1) v += __shfl_down_sync(0xFFFFFFFFu, v, o);
        if ((t & 31) == 0) s_part[t >> 5] = v;
    }
    __syncthreads();
    if (t == 0) s_off = s_part[0] + s_part[1] + s_part[2] + s_part[3];
    __syncthreads();
    int idx = bid * SCAN_T + t;
    if (idx < N_NODES) g_indptr[idx] += s_off;
    if (idx == 0) g_indptr[N_NODES] = N_EDGES;
}

__global__ void k_scatter(const void* __restrict__ ei) {
    int is64 = probe_is64((const unsigned*)ei, threadIdx.x);
    int e = blockIdx.x * blockDim.x + threadIdx.x;
    if (e < N_EDGES) {
        int src = edge_at(ei, e, is64);
        int dst = edge_at(ei, N_EDGES + e, is64);
        if ((unsigned)src < N_NODES && (unsigned)dst < N_NODES) {
            int pos = g_indptr[dst] + atomicAdd(&g_cursor[dst], 1);
            unsigned wbits = __float_as_uint(g_dinv[src]);
            g_edges[pos] = ((unsigned long long)wbits << 32) | (unsigned)src;
        }
    }
}

// ---------------- SpMM (pull, warp-per-node, half2 per lane, MLP=8) ---------
// R10/R13 body EXACT — protected. Full grid (warp per node): R15 proved low
// occupancy starves latency hiding (+100us); R11/R12 proved manual loop
// restructures regress. Do not touch.
// out[i] = dinv[i] * ( sum_e dinv[src_e] * h[src_e] + dinv[i] * h[i] )
__global__ void __launch_bounds__(256)
k_prop(int sel_in, int sel_out) {
    const unsigned* hin  = g_h[sel_in];
    unsigned*       hout = g_h[sel_out];

    int gw   = (blockIdx.x * blockDim.x + threadIdx.x) >> 5;
    int lane = threadIdx.x & 31;
    if (gw >= N_NODES) return;

    int beg = g_indptr[gw];
    int end = g_indptr[gw + 1];

    float ax = 0.f, ay = 0.f;
    int e = beg;
    for (; e + 8 <= end; e += 8) {
        unsigned long long p0 = __ldg(&g_edges[e]);
        unsigned long long p1 = __ldg(&g_edges[e + 1]);
        unsigned long long p2 = __ldg(&g_edges[e + 2]);
        unsigned long long p3 = __ldg(&g_edges[e + 3]);
        unsigned long long p4 = __ldg(&g_edges[e + 4]);
        unsigned long long p5 = __ldg(&g_edges[e + 5]);
        unsigned long long p6 = __ldg(&g_edges[e + 6]);
        unsigned long long p7 = __ldg(&g_edges[e + 7]);
        unsigned u0 = __ldg(&hin[((int)(unsigned)p0) * 32 + lane]);
        unsigned u1 = __ldg(&hin[((int)(unsigned)p1) * 32 + lane]);
        unsigned u2 = __ldg(&hin[((int)(unsigned)p2) * 32 + lane]);
        unsigned u3 = __ldg(&hin[((int)(unsigned)p3) * 32 + lane]);
        unsigned u4 = __ldg(&hin[((int)(unsigned)p4) * 32 + lane]);
        unsigned u5 = __ldg(&hin[((int)(unsigned)p5) * 32 + lane]);
        unsigned u6 = __ldg(&hin[((int)(unsigned)p6) * 32 + lane]);
        unsigned u7 = __ldg(&hin[((int)(unsigned)p7) * 32 + lane]);
        float w0 = __uint_as_float((unsigned)(p0 >> 32));
        float w1 = __uint_as_float((unsigned)(p1 >> 32));
        float w2 = __uint_as_float((unsigned)(p2 >> 32));
        float w3 = __uint_as_float((unsigned)(p3 >> 32));
        float w4 = __uint_as_float((unsigned)(p4 >> 32));
        float w5 = __uint_as_float((unsigned)(p5 >> 32));
        float w6 = __uint_as_float((unsigned)(p6 >> 32));
        float w7 = __uint_as_float((unsigned)(p7 >> 32));
        float2 f0 = __half22float2(h2_of(u0));
        float2 f1 = __half22float2(h2_of(u1));
        float2 f2 = __half22float2(h2_of(u2));
        float2 f3 = __half22float2(h2_of(u3));
        float2 f4 = __half22float2(h2_of(u4));
        float2 f5 = __half22float2(h2_of(u5));
        float2 f6 = __half22float2(h2_of(u6));
        float2 f7 = __half22float2(h2_of(u7));
        ax = fmaf(w0, f0.x, ax); ay = fmaf(w0, f0.y, ay);
        ax = fmaf(w1, f1.x, ax); ay = fmaf(w1, f1.y, ay);
        ax = fmaf(w2, f2.x, ax); ay = fmaf(w2, f2.y, ay);
        ax = fmaf(w3, f3.x, ax); ay = fmaf(w3, f3.y, ay);
        ax = fmaf(w4, f4.x, ax); ay = fmaf(w4, f4.y, ay);
        ax = fmaf(w5, f5.x, ax); ay = fmaf(w5, f5.y, ay);
        ax = fmaf(w6, f6.x, ax); ay = fmaf(w6, f6.y, ay);
        ax = fmaf(w7, f7.x, ax); ay = fmaf(w7, f7.y, ay);
    }
    for (; e < end; e++) {
        unsigned long long p = __ldg(&g_edges[e]);
        float2 f = __half22float2(h2_of(__ldg(&hin[((int)(unsigned)p) * 32 + lane])));
        float w = __uint_as_float((unsigned)(p >> 32));
        ax = fmaf(w, f.x, ax); ay = fmaf(w, f.y, ay);
    }

    float di = g_dinv[gw];
    float2 self = __half22float2(h2_of(__ldg(&hin[gw * 32 + lane])));
    ax = di * fmaf(di, self.x, ax);
    ay = di * fmaf(di, self.y, ay);
    hout[gw * 32 + lane] = u_of(__floats2half2_rn(ax, ay));
}

// ---------------- weight folding: K=384 -> K=256, fp16, B-pair layout --------
// out = x*A + P1*B + P3*C + P7*D
__device__ __forceinline__ float fold_w(const float* W, int s, int k, int j) {
    float w0 = W[(0   + k) * 64 + j];
    float w1 = W[(64  + k) * 64 + j];
    float w2 = W[(128 + k) * 64 + j];
    float w3 = W[(192 + k) * 64 + j];
    float w4 = W[(256 + k) * 64 + j];
    float w5 = W[(320 + k) * 64 + j];
    if (s == 0) return w3;
    if (s == 1) return w0 - w3 + w4;
    if (s == 2) return w1 - w4 + w5;
    return w2 - w5;
}

__global__ void k_comb(const float* __restrict__ W) {
    int idx = blockIdx.x * blockDim.x + threadIdx.x;   // 4*64*4*4 = 4096
    if (idx >= 4 * 64 * 4 * 4) return;
    int s   = idx >> 10;
    int n   = (idx >> 4) & 63;
    int kk  = (idx >> 2) & 3;
    int th4 = idx & 3;
    int kc0 = kk * 8 + th4;       // b0 column-chunk
    int kc1 = kc0 + 4;            // b1 column-chunk
    uint2 p;
    p.x = u_of(__floats2half2_rn(fold_w(W, s, 2 * kc0, n), fold_w(W, s, 2 * kc0 + 1, n)));
    p.y = u_of(__floats2half2_rn(fold_w(W, s, 2 * kc1, n), fold_w(W, s, 2 * kc1 + 1, n)));
    g_Wp[idx] = p;
}

// ---------------- HMMA output GEMM + counter reset ---------------------------
// block = 256 thr (8 warps), each warp: 16 rows x 64 cols, mma.m16n8k16 f16->f32
// Also re-zeroes g_deg/g_cursor for the next replay (they were last consumed
// by k_scan1/k_scatter this launch; no sync needed).
__global__ void __launch_bounds__(256)
k_gemm(const float* __restrict__ bias, float* __restrict__ out) {
    // counter reset for next invocation (deterministic replay state)
    {
        int tid  = blockIdx.x * blockDim.x + threadIdx.x;
        int nthr = gridDim.x * blockDim.x;
        for (int i = tid; i < N_NODES; i += nthr) { g_deg[i] = 0; g_cursor[i] = 0; }
    }

    int w    = threadIdx.x >> 5;
    int t    = threadIdx.x & 31;
    int m0   = blockIdx.x * 128 + w * 16;
    int quad = t >> 2;          // 0..7
    int th4  = t & 3;           // 0..3

    int r0 = m0 + quad;
    int r1 = r0 + 8;
    int r0c = (r0 < N_NODES) ? r0 : 0;   // clamped for loads
    int r1c = (r1 < N_NODES) ? r1 : 0;

    float acc[8][4];
#pragma unroll
    for (int nt = 0; nt < 8; nt++)
#pragma unroll
        for (int i = 0; i < 4; i++) acc[nt][i] = 0.f;

    const int plane_sel[4] = {0, 1, 2, 4};
#pragma unroll
    for (int s = 0; s < 4; s++) {
        const unsigned* plane = g_h[plane_sel[s]];
        const uint2* Wb = &g_Wp[s * 64 * 16];
#pragma unroll
        for (int kk = 0; kk < 4; kk++) {
            int c0 = kk * 8 + th4;
            unsigned a0 = __ldg(&plane[r0c * 32 + c0]);
            unsigned a1 = __ldg(&plane[r1c * 32 + c0]);
            unsigned a2 = __ldg(&plane[r0c * 32 + c0 + 4]);
            unsigned a3 = __ldg(&plane[r1c * 32 + c0 + 4]);
#pragma unroll
            for (int nt = 0; nt < 8; nt++) {
                int n = nt * 8 + quad;
                uint2 bb = __ldg(&Wb[n * 16 + kk * 4 + th4]);
                asm volatile(
                    "mma.sync.aligned.m16n8k16.row.col.f32.f16.f16.f32 "
                    "{%0,%1,%2,%3}, {%4,%5,%6,%7}, {%8,%9}, {%0,%1,%2,%3};"
                    : "+f"(acc[nt][0]), "+f"(acc[nt][1]),
                      "+f"(acc[nt][2]), "+f"(acc[nt][3])
                    : "r"(a0), "r"(a1), "r"(a2), "r"(a3), "r"(bb.x), "r"(bb.y));
            }
        }
    }

#pragma unroll
    for (int nt = 0; nt < 8; nt++) {
        int col = nt * 8 + th4 * 2;
        float2 bj = __ldg((const float2*)&bias[col]);
        if (r0 < N_NODES) {
            float v0 = acc[nt][0] + bj.x;
            float v1 = acc[nt][1] + bj.y;
            float2 o; o.x = v0 > 0.f ? v0 : 0.f; o.y = v1 > 0.f ? v1 : 0.f;
            *(float2*)&out[r0 * 64 + col] = o;
        }
        if (r1 < N_NODES) {
            float v2 = acc[nt][2] + bj.x;
            float v3 = acc[nt][3] + bj.y;
            float2 o; o.x = v2 > 0.f ? v2 : 0.f; o.y = v3 > 0.f ? v3 : 0.f;
            *(float2*)&out[r1 * 64 + col] = o;
        }
    }
}

// ---------------- launch ----------------
extern "C" void kernel_launch(void* const* d_in, const int* in_sizes, int n_in,
                              void* d_out, int out_size) {
    const float* x  = (const float*)d_in[0];
    const void*  ei = d_in[1];
    const float* W  = (const float*)d_in[2];
    const float* b  = (const float*)d_in[3];
    float* out = (float*)d_out;

    int nb_edges = (N_EDGES + 255) / 256;
    int nb_scan  = (N_NODES + SCAN_T - 1) / SCAN_T;

    // CSR prologue (4 launches; hist fused into init, counters pre-zeroed)
    k_init_hist<<<2048, 256>>>(ei, x);                 // 0: x->fp16 + degree hist
    k_scan1<<<nb_scan, SCAN_T>>>();                    // 1
    k_scanfix<<<nb_scan, SCAN_T>>>();                  // 2
    k_scatter<<<nb_edges, 256>>>(ei);                  // 3

    // 7 propagations: save P^1 (plane1), P^3 (plane2), end at P^7 (plane4)
    int nb_prop = (N_NODES * 32 + 255) / 256;          // warp per node (full grid)
    k_prop<<<nb_prop, 256>>>(0, 1);   // X  -> P1
    k_prop<<<nb_prop, 256>>>(1, 3);   // P1 -> A   (P^2)
    k_prop<<<nb_prop, 256>>>(3, 2);   // A  -> P3  (P^3)
    k_prop<<<nb_prop, 256>>>(2, 3);   // P3 -> A   (P^4)
    k_prop<<<nb_prop, 256>>>(3, 4);   // A  -> B   (P^5)
    k_prop<<<nb_prop, 256>>>(4, 3);   // B  -> A   (P^6)
    k_prop<<<nb_prop, 256>>>(3, 4);   // A  -> B   (P^7)

    k_comb<<<16, 256>>>(W);
    k_gemm<<<(N_NODES + 127) / 128, 256>>>(b, out);
}

// round 17
// speedup vs baseline: 1.4034x; 1.0644x over previous
#include <cuda_runtime.h>
#include <cuda_fp16.h>

#define N_NODES 100000
#define N_EDGES 1600000
#define DIM 64
#define SCAN_T 1024

// ---------------- device scratch (static, no allocation) ----------------
// g_deg / g_cursor are zero on first use (static zero-init) and re-zeroed at
// the END of every kernel_launch (inside k_gemm), keeping replays deterministic.
__device__ int      g_deg[N_NODES];
__device__ int      g_cursor[N_NODES];
__device__ float    g_dinv[N_NODES];    // 1/sqrt(deg+1)  (z-init)
__device__ float    g_idg[N_NODES];     // 1/(deg+1)      (prop epilogue)
__device__ float    g_sdeg[N_NODES];    // sqrt(deg+1)    (GEMM row scale)
__device__ int      g_indptr[N_NODES + 1];
__device__ int      g_bsum[128];
__device__ unsigned g_edges[N_EDGES];   // src index only (z-space: no weight)
// 5 feature planes in fp16 (raw u32 = 2 halves): z-space. 0:z0 1:z1 2:z3 3:A 4:z7
__device__ unsigned g_h[5][N_NODES * 32];
// folded weights, fp16, B-fragment-paired: [s][n][kk][th4]
__device__ uint2    g_Wp[4 * 64 * 4 * 4];

__device__ __forceinline__ __half2 h2_of(unsigned u) {
    return *reinterpret_cast<__half2*>(&u);
}
__device__ __forceinline__ unsigned u_of(__half2 h) {
    return *reinterpret_cast<unsigned*>(&h);
}

// Block-local dtype probe: for int64 node indices < 100000 (LE), every odd
// 32-bit word of edge_index is 0.
__device__ __forceinline__ int probe_is64(const unsigned* w, int lane_tid) {
    __shared__ int s_is64;
    if (lane_tid < 32) {
        unsigned v = w[2 * lane_tid + 1];
        unsigned any = __ballot_sync(0xFFFFFFFFu, v != 0);
        if (lane_tid == 0) s_is64 = (any == 0) ? 1 : 0;
    }
    __syncthreads();
    return s_is64;
}

__device__ __forceinline__ int edge_at(const void* ei, int idx, int is64) {
    if (is64) return (int)((const long long*)ei)[idx];
    return ((const int*)ei)[idx];
}

// ---------------- degree histogram (g_deg arrives zeroed) --------------------
__global__ void k_hist(const void* __restrict__ ei) {
    int is64 = probe_is64((const unsigned*)ei, threadIdx.x);
    int tid  = blockIdx.x * blockDim.x + threadIdx.x;
    int nthr = gridDim.x * blockDim.x;
    for (int e = tid; e < N_EDGES; e += nthr) {
        int dst = edge_at(ei, N_EDGES + e, is64);
        if ((unsigned)dst < N_NODES) atomicAdd(&g_deg[dst], 1);
    }
}

// ---------------- CSR build ----------------
__global__ void k_scan1() {
    __shared__ int s[SCAN_T];
    int t = threadIdx.x;
    int idx = blockIdx.x * SCAN_T + t;
    int v = (idx < N_NODES) ? g_deg[idx] : 0;
    s[t] = v;
    __syncthreads();
    for (int off = 1; off < SCAN_T; off <<= 1) {
        int xv = (t >= off) ? s[t - off] : 0;
        __syncthreads();
        s[t] += xv;
        __syncthreads();
    }
    if (idx < N_NODES) {
        g_indptr[idx] = s[t] - v;                          // local exclusive
        float dt = (float)(v + 1);                          // +1 self-loop
        g_dinv[idx] = rsqrtf(dt);
        g_idg[idx]  = 1.0f / dt;
        g_sdeg[idx] = sqrtf(dt);
    }
    if (t == SCAN_T - 1) g_bsum[blockIdx.x] = s[t];
}

// parallel cross-block offset: threads 0..127 reduce g_bsum[0..bid-1]
__global__ void k_scanfix() {
    __shared__ int s_part[4];
    __shared__ int s_off;
    int t   = threadIdx.x;
    int bid = blockIdx.x;
    if (t < 128) {
        int v = (t < bid) ? g_bsum[t] : 0;
#pragma unroll
        for (int o = 16; o > 0; o >>= 1) v += __shfl_down_sync(0xFFFFFFFFu, v, o);
        if ((t & 31) == 0) s_part[t >> 5] = v;
    }
    __syncthreads();
    if (t == 0) s_off = s_part[0] + s_part[1] + s_part[2] + s_part[3];
    __syncthreads();
    int idx = bid * SCAN_T + t;
    if (idx < N_NODES) g_indptr[idx] += s_off;
    if (idx == 0) g_indptr[N_NODES] = N_EDGES;
}

// ---------------- z-init: plane0 = dinv ⊙ x (fp16) ---------------------------
__global__ void k_zscale(const float* __restrict__ x) {
    int tid  = blockIdx.x * blockDim.x + threadIdx.x;
    int nthr = gridDim.x * blockDim.x;
    const float2* x2 = (const float2*)x;
    for (int i = tid; i < N_NODES * 32; i += nthr) {
        float d = g_dinv[i >> 5];
        float2 v = x2[i];
        g_h[0][i] = u_of(__floats2half2_rn(v.x * d, v.y * d));
    }
}

// ---------------- scatter: src index only (4B) -------------------------------
__global__ void k_scatter(const void* __restrict__ ei) {
    int is64 = probe_is64((const unsigned*)ei, threadIdx.x);
    int e = blockIdx.x * blockDim.x + threadIdx.x;
    if (e < N_EDGES) {
        int src = edge_at(ei, e, is64);
        int dst = edge_at(ei, N_EDGES + e, is64);
        if ((unsigned)src < N_NODES && (unsigned)dst < N_NODES) {
            int pos = g_indptr[dst] + atomicAdd(&g_cursor[dst], 1);
            g_edges[pos] = (unsigned)src;
        }
    }
}

// ---------------- SpMM (pull, warp-per-node, z-space, MLP=8) -----------------
// Protected structure (R10): 8 edge loads + 8 gathers per chunk, full grid.
// z_out[i] = ( sum_e z[src_e] + z[i] ) * (1/deg_i)
__global__ void __launch_bounds__(256)
k_prop(int sel_in, int sel_out) {
    const unsigned* hin  = g_h[sel_in];
    unsigned*       hout = g_h[sel_out];

    int gw   = (blockIdx.x * blockDim.x + threadIdx.x) >> 5;
    int lane = threadIdx.x & 31;
    if (gw >= N_NODES) return;

    int beg = g_indptr[gw];
    int end = g_indptr[gw + 1];

    float ax = 0.f, ay = 0.f;
    int e = beg;
    for (; e + 8 <= end; e += 8) {
        unsigned s0 = __ldg(&g_edges[e]);
        unsigned s1 = __ldg(&g_edges[e + 1]);
        unsigned s2 = __ldg(&g_edges[e + 2]);
        unsigned s3 = __ldg(&g_edges[e + 3]);
        unsigned s4 = __ldg(&g_edges[e + 4]);
        unsigned s5 = __ldg(&g_edges[e + 5]);
        unsigned s6 = __ldg(&g_edges[e + 6]);
        unsigned s7 = __ldg(&g_edges[e + 7]);
        unsigned u0 = __ldg(&hin[s0 * 32 + lane]);
        unsigned u1 = __ldg(&hin[s1 * 32 + lane]);
        unsigned u2 = __ldg(&hin[s2 * 32 + lane]);
        unsigned u3 = __ldg(&hin[s3 * 32 + lane]);
        unsigned u4 = __ldg(&hin[s4 * 32 + lane]);
        unsigned u5 = __ldg(&hin[s5 * 32 + lane]);
        unsigned u6 = __ldg(&hin[s6 * 32 + lane]);
        unsigned u7 = __ldg(&hin[s7 * 32 + lane]);
        float2 f0 = __half22float2(h2_of(u0));
        float2 f1 = __half22float2(h2_of(u1));
        float2 f2 = __half22float2(h2_of(u2));
        float2 f3 = __half22float2(h2_of(u3));
        float2 f4 = __half22float2(h2_of(u4));
        float2 f5 = __half22float2(h2_of(u5));
        float2 f6 = __half22float2(h2_of(u6));
        float2 f7 = __half22float2(h2_of(u7));
        ax += f0.x; ay += f0.y;
        ax += f1.x; ay += f1.y;
        ax += f2.x; ay += f2.y;
        ax += f3.x; ay += f3.y;
        ax += f4.x; ay += f4.y;
        ax += f5.x; ay += f5.y;
        ax += f6.x; ay += f6.y;
        ax += f7.x; ay += f7.y;
    }
    for (; e < end; e++) {
        unsigned s = __ldg(&g_edges[e]);
        float2 f = __half22float2(h2_of(__ldg(&hin[s * 32 + lane])));
        ax += f.x; ay += f.y;
    }

    float idg = g_idg[gw];
    float2 self = __half22float2(h2_of(__ldg(&hin[gw * 32 + lane])));
    ax = (ax + self.x) * idg;
    ay = (ay + self.y) * idg;
    hout[gw * 32 + lane] = u_of(__floats2half2_rn(ax, ay));
}

// ---------------- weight folding: K=384 -> K=256, fp16, B-pair layout --------
// out = x*A + P1*B + P3*C + P7*D
__device__ __forceinline__ float fold_w(const float* W, int s, int k, int j) {
    float w0 = W[(0   + k) * 64 + j];
    float w1 = W[(64  + k) * 64 + j];
    float w2 = W[(128 + k) * 64 + j];
    float w3 = W[(192 + k) * 64 + j];
    float w4 = W[(256 + k) * 64 + j];
    float w5 = W[(320 + k) * 64 + j];
    if (s == 0) return w3;
    if (s == 1) return w0 - w3 + w4;
    if (s == 2) return w1 - w4 + w5;
    return w2 - w5;
}

__global__ void k_comb(const float* __restrict__ W) {
    int idx = blockIdx.x * blockDim.x + threadIdx.x;   // 4*64*4*4 = 4096
    if (idx >= 4 * 64 * 4 * 4) return;
    int s   = idx >> 10;
    int n   = (idx >> 4) & 63;
    int kk  = (idx >> 2) & 3;
    int th4 = idx & 3;
    int kc0 = kk * 8 + th4;       // b0 column-chunk
    int kc1 = kc0 + 4;            // b1 column-chunk
    uint2 p;
    p.x = u_of(__floats2half2_rn(fold_w(W, s, 2 * kc0, n), fold_w(W, s, 2 * kc0 + 1, n)));
    p.y = u_of(__floats2half2_rn(fold_w(W, s, 2 * kc1, n), fold_w(W, s, 2 * kc1 + 1, n)));
    g_Wp[idx] = p;
}

// ---------------- HMMA output GEMM + counter reset ---------------------------
// A-fragments are z-plane values scaled by sqrt(deg) per row (h = sdeg * z;
// for plane0, sdeg*z0 == x). Also re-zeroes g_deg/g_cursor for next replay.
__global__ void __launch_bounds__(256)
k_gemm(const float* __restrict__ bias, float* __restrict__ out) {
    // counter reset for next invocation (deterministic replay state)
    {
        int tid  = blockIdx.x * blockDim.x + threadIdx.x;
        int nthr = gridDim.x * blockDim.x;
        for (int i = tid; i < N_NODES; i += nthr) { g_deg[i] = 0; g_cursor[i] = 0; }
    }

    int w    = threadIdx.x >> 5;
    int t    = threadIdx.x & 31;
    int m0   = blockIdx.x * 128 + w * 16;
    int quad = t >> 2;          // 0..7
    int th4  = t & 3;           // 0..3

    int r0 = m0 + quad;
    int r1 = r0 + 8;
    int r0c = (r0 < N_NODES) ? r0 : 0;   // clamped for loads
    int r1c = (r1 < N_NODES) ? r1 : 0;

    __half2 sd0 = __float2half2_rn(__ldg(&g_sdeg[r0c]));
    __half2 sd1 = __float2half2_rn(__ldg(&g_sdeg[r1c]));

    float acc[8][4];
#pragma unroll
    for (int nt = 0; nt < 8; nt++)
#pragma unroll
        for (int i = 0; i < 4; i++) acc[nt][i] = 0.f;

    const int plane_sel[4] = {0, 1, 2, 4};
#pragma unroll
    for (int s = 0; s < 4; s++) {
        const unsigned* plane = g_h[plane_sel[s]];
        const uint2* Wb = &g_Wp[s * 64 * 16];
#pragma unroll
        for (int kk = 0; kk < 4; kk++) {
            int c0 = kk * 8 + th4;
            unsigned a0 = u_of(__hmul2(h2_of(__ldg(&plane[r0c * 32 + c0])), sd0));
            unsigned a1 = u_of(__hmul2(h2_of(__ldg(&plane[r1c * 32 + c0])), sd1));
            unsigned a2 = u_of(__hmul2(h2_of(__ldg(&plane[r0c * 32 + c0 + 4])), sd0));
            unsigned a3 = u_of(__hmul2(h2_of(__ldg(&plane[r1c * 32 + c0 + 4])), sd1));
#pragma unroll
            for (int nt = 0; nt < 8; nt++) {
                int n = nt * 8 + quad;
                uint2 bb = __ldg(&Wb[n * 16 + kk * 4 + th4]);
                asm volatile(
                    "mma.sync.aligned.m16n8k16.row.col.f32.f16.f16.f32 "
                    "{%0,%1,%2,%3}, {%4,%5,%6,%7}, {%8,%9}, {%0,%1,%2,%3};"
                    : "+f"(acc[nt][0]), "+f"(acc[nt][1]),
                      "+f"(acc[nt][2]), "+f"(acc[nt][3])
                    : "r"(a0), "r"(a1), "r"(a2), "r"(a3), "r"(bb.x), "r"(bb.y));
            }
        }
    }

#pragma unroll
    for (int nt = 0; nt < 8; nt++) {
        int col = nt * 8 + th4 * 2;
        float2 bj = __ldg((const float2*)&bias[col]);
        if (r0 < N_NODES) {
            float v0 = acc[nt][0] + bj.x;
            float v1 = acc[nt][1] + bj.y;
            float2 o; o.x = v0 > 0.f ? v0 : 0.f; o.y = v1 > 0.f ? v1 : 0.f;
            *(float2*)&out[r0 * 64 + col] = o;
        }
        if (r1 < N_NODES) {
            float v2 = acc[nt][2] + bj.x;
            float v3 = acc[nt][3] + bj.y;
            float2 o; o.x = v2 > 0.f ? v2 : 0.f; o.y = v3 > 0.f ? v3 : 0.f;
            *(float2*)&out[r1 * 64 + col] = o;
        }
    }
}

// ---------------- launch ----------------
extern "C" void kernel_launch(void* const* d_in, const int* in_sizes, int n_in,
                              void* d_out, int out_size) {
    const float* x  = (const float*)d_in[0];
    const void*  ei = d_in[1];
    const float* W  = (const float*)d_in[2];
    const float* b  = (const float*)d_in[3];
    float* out = (float*)d_out;

    int nb_edges = (N_EDGES + 255) / 256;
    int nb_scan  = (N_NODES + SCAN_T - 1) / SCAN_T;

    // CSR prologue
    k_hist<<<2048, 256>>>(ei);                         // 0: degree histogram
    k_scan1<<<nb_scan, SCAN_T>>>();                    // 1
    k_scanfix<<<nb_scan, SCAN_T>>>();                  // 2
    k_zscale<<<512, 256>>>(x);                         // 3: plane0 = dinv*x
    k_scatter<<<nb_edges, 256>>>(ei);                  // 4

    // 7 propagations (z-space): save z1 (plane1), z3 (plane2), end z7 (plane4)
    int nb_prop = (N_NODES * 32 + 255) / 256;          // warp per node (full grid)
    k_prop<<<nb_prop, 256>>>(0, 1);   // z0 -> z1
    k_prop<<<nb_prop, 256>>>(1, 3);   // z1 -> A   (z2)
    k_prop<<<nb_prop, 256>>>(3, 2);   // A  -> z3
    k_prop<<<nb_prop, 256>>>(2, 3);   // z3 -> A   (z4)
    k_prop<<<nb_prop, 256>>>(3, 4);   // A  -> B   (z5)
    k_prop<<<nb_prop, 256>>>(4, 3);   // B  -> A   (z6)
    k_prop<<<nb_prop, 256>>>(3, 4);   // A  -> B   (z7)

    k_comb<<<16, 256>>>(W);
    k_gemm<<<(N_NODES + 127) / 128, 256>>>(b, out);
}